// round 12
// baseline (speedup 1.0000x reference)
#include <cuda_runtime.h>
#include <cuda_fp16.h>
#include <math.h>
#include <stdint.h>

#define BQ        16384
#define OBJ_FEAT  1024
#define PVF_DIM   1024
#define PPF_DIM   64
#define HIDDEN    512
#define OBJ_NUM   1001
#define PRED_NUM  132

#define OBJ_PAD   1024
#define PRED_PAD  256
#define MBLK      (BQ / 128)                    // 128 m-blocks

// ---------------- scratch (__device__ globals; allocation-free rule) --------
__device__ __half g_sfh[(size_t)BQ * OBJ_FEAT];
__device__ __half g_ofh[(size_t)BQ * OBJ_FEAT];
__device__ __half g_pvfh[(size_t)BQ * PVF_DIM];
__device__ __half g_ppfh[(size_t)BQ * PPF_DIM];
__device__ __half g_Hs[(size_t)BQ * HIDDEN];
__device__ __half g_Ho[(size_t)BQ * HIDDEN];
__device__ __half g_Hv[(size_t)BQ * HIDDEN];
__device__ __half g_Hp[(size_t)BQ * HIDDEN];
__device__ __half g_Wt1[(size_t)HIDDEN * OBJ_FEAT];
__device__ __half g_Wtv[(size_t)HIDDEN * PVF_DIM];
__device__ __half g_Wtf[(size_t)HIDDEN * (HIDDEN + PPF_DIM)];
__device__ __half g_Wt2[(size_t)OBJ_PAD * HIDDEN];
__device__ __half g_Wtp[(size_t)PRED_PAD * HIDDEN];

// completion counters (cleared by clearflags each replay)
__device__ int g_wcnt[6];                       // 5 weights + ppf conv
__device__ int g_conv[3 * MBLK];                // per (z, mb) input conversion
__device__ int g_cnt_s1[3 * MBLK];              // s1 outputs, 4 n-tiles each
__device__ int g_cnt_pf[MBLK];                  // pf outputs, 4 n-tiles each

// ---------------- PTX helpers ----------------
__device__ __forceinline__ uint32_t smem_u32(const void* p) {
    uint32_t a;
    asm("{ .reg .u64 t; cvta.to.shared.u64 t, %1; cvt.u32.u64 %0, t; }" : "=r"(a) : "l"(p));
    return a;
}
__device__ __forceinline__ void mma_f16(float* c, const uint32_t* a, const uint32_t* b) {
    asm volatile(
        "mma.sync.aligned.m16n8k16.row.col.f32.f16.f16.f32 "
        "{%0,%1,%2,%3}, {%4,%5,%6,%7}, {%8,%9}, {%0,%1,%2,%3};"
        : "+f"(c[0]), "+f"(c[1]), "+f"(c[2]), "+f"(c[3])
        : "r"(a[0]), "r"(a[1]), "r"(a[2]), "r"(a[3]), "r"(b[0]), "r"(b[1]));
}
#define LDSM_X4(r0, r1, r2, r3, addr) \
    asm volatile("ldmatrix.sync.aligned.m8n8.x4.shared.b16 {%0,%1,%2,%3}, [%4];" \
        : "=r"(r0), "=r"(r1), "=r"(r2), "=r"(r3) : "r"(addr))
__device__ __forceinline__ void cp16cg(uint32_t dst, const void* src) {
    asm volatile("cp.async.cg.shared.global [%0], [%1], 16;" :: "r"(dst), "l"(src));
}
__device__ __forceinline__ void cp16ca(uint32_t dst, const void* src) {
    asm volatile("cp.async.ca.shared.global [%0], [%1], 16;" :: "r"(dst), "l"(src));
}
#define CP_COMMIT() asm volatile("cp.async.commit_group;" ::: "memory")
#define CP_WAIT(n)  asm volatile("cp.async.wait_group %0;" :: "n"(n) : "memory")

__device__ __forceinline__ void signal_done(int* c) {
    __threadfence();
    __syncthreads();
    if (threadIdx.x == 0) atomicAdd(c, 1);
}
// up to 3 counters; pass nullptr to skip
__device__ __forceinline__ void waits(int* c0, int t0, int* c1, int t1,
                                      int* c2, int t2) {
    if (threadIdx.x == 0) {
        if (c0) while (atomicAdd(c0, 0) < t0) __nanosleep(64);
        if (c1) while (atomicAdd(c1, 0) < t1) __nanosleep(64);
        if (c2) while (atomicAdd(c2, 0) < t2) __nanosleep(64);
        __threadfence();
    }
    __syncthreads();
}

// ---------------- smem layout: 3 stages, A/B tiles [128 rows][64+8 halves] --
#define ROWB      144
#define T_STAGE   (128 * ROWB)                  // 18432 B
#define STAGE_B   (2 * T_STAGE)                 // 36864 B
#define NSTAGE    3
#define SMEM_BYTES (NSTAGE * STAGE_B)           // 110592 B

// ---------------- flag clear (tiny kernel, runs first each replay) ---------
__global__ void clearflags() {
    const int i = threadIdx.x;
    if (i < 6) g_wcnt[i] = 0;
    for (int j = i; j < 3 * MBLK; j += 256) { g_conv[j] = 0; g_cnt_s1[j] = 0; }
    for (int j = i; j < MBLK; j += 256) g_cnt_pf[j] = 0;
}

// ---------------- prep device helpers ----------------
__device__ void transpose_slice(char* smem, const float* __restrict__ W,
                                __half* __restrict__ Wt,
                                int K, int N, int Npad, int slice, int nsl) {
    float (*t)[33] = reinterpret_cast<float(*)[33]>(smem);
    const int tx5 = threadIdx.x & 31, ty3 = threadIdx.x >> 5;  // (32, 8)
    const int ntx = Npad / 32, nty = (K + 31) / 32;
    for (int tile = slice; tile < ntx * nty; tile += nsl) {
        const int bx = (tile % ntx) * 32;   // n
        const int by = (tile / ntx) * 32;   // k
#pragma unroll
        for (int j = 0; j < 32; j += 8) {
            const int y = by + ty3 + j, x = bx + tx5;
            t[ty3 + j][tx5] = (x < N && y < K) ? W[(size_t)y * N + x] : 0.0f;
        }
        __syncthreads();
#pragma unroll
        for (int j = 0; j < 32; j += 8) {
            const int row = bx + ty3 + j, col = by + tx5;
            if (row < Npad && col < K)
                Wt[(size_t)row * K + col] = __float2half(t[tx5][ty3 + j]);
        }
        __syncthreads();
    }
}

__device__ void conv_units(const float* __restrict__ in, __half* __restrict__ out,
                           size_t u0, int nunits) {
    for (int i = threadIdx.x; i < nunits; i += 256) {
        const size_t u = u0 + i;
        const float4 a = *reinterpret_cast<const float4*>(in + u * 8);
        const float4 b = *reinterpret_cast<const float4*>(in + u * 8 + 4);
        __half2 h[4];
        h[0] = __floats2half2_rn(a.x, a.y);
        h[1] = __floats2half2_rn(a.z, a.w);
        h[2] = __floats2half2_rn(b.x, b.y);
        h[3] = __floats2half2_rn(b.z, b.w);
        *reinterpret_cast<uint4*>(out + u * 8) = *reinterpret_cast<uint4*>(h);
    }
}

// ================= round-6 champion GEMM core (unchanged) ==================
struct GemmCore {
    uint32_t sbase;
    int tid, lane, grp, t4, mW, nW;
    uint32_t offA, offB;
    int ldRow, ldQ0;

    __device__ __forceinline__ void init(uint32_t sb) {
        sbase = sb;
        tid = threadIdx.x;
        const int wid = tid >> 5;
        lane = tid & 31;
        grp = lane >> 2; t4 = lane & 3;
        const int wy = wid >> 2, wx = wid & 3;     // warp grid 2x4
        mW = wy * 64; nW = wx * 32;
        offA = (uint32_t)(lane & 15) * ROWB + (uint32_t)(lane >> 4) * 16;
        const uint32_t bR = (uint32_t)((lane & 7) + ((lane >> 4) & 1) * 8);
        offB = bR * ROWB + (uint32_t)((lane >> 3) & 1) * 16;
        ldRow = tid >> 1;
        ldQ0 = (tid & 1) * 4;
    }

    __device__ __forceinline__ void load_stage(const __half* __restrict__ A,
                                               const __half* __restrict__ A2,
                                               const __half* __restrict__ Bt,
                                               int m0, int n0, int K,
                                               int kc, int s) const {
        const uint32_t abase = sbase + s * STAGE_B;
        const uint32_t bbase = abase + T_STAGE;
#pragma unroll
        for (int i = 0; i < 4; i++) {
            const int q = ldQ0 + i;
            const int k = kc + q * 8;
            const uint32_t dst = abase + (uint32_t)ldRow * ROWB + (uint32_t)q * 16;
            const __half* src = (k < HIDDEN)
                ? (A  + (size_t)(m0 + ldRow) * HIDDEN + k)
                : (A2 + (size_t)(m0 + ldRow) * PPF_DIM + (k - HIDDEN));
            cp16cg(dst, src);
        }
#pragma unroll
        for (int i = 0; i < 4; i++) {
            const int q = ldQ0 + i;
            const uint32_t dst = bbase + (uint32_t)ldRow * ROWB + (uint32_t)q * 16;
            cp16ca(dst, Bt + (size_t)(n0 + ldRow) * K + kc + q * 8);
        }
    }

    __device__ __forceinline__ void load_stageP(const __half* __restrict__ A,
                                                const __half* __restrict__ Bt,
                                                int m0, int n0, int K,
                                                int kc, int s) const {
        const uint32_t abase = sbase + s * STAGE_B;
        const uint32_t bbase = abase + T_STAGE;
#pragma unroll
        for (int i = 0; i < 4; i++) {
            const int q = ldQ0 + i;
            const uint32_t dst = abase + (uint32_t)ldRow * ROWB + (uint32_t)q * 16;
            cp16cg(dst, A + (size_t)(m0 + ldRow) * K + kc + q * 8);
        }
#pragma unroll
        for (int i = 0; i < 4; i++) {
            const int q = ldQ0 + i;
            const uint32_t dst = bbase + (uint32_t)ldRow * ROWB + (uint32_t)q * 16;
            cp16ca(dst, Bt + (size_t)(n0 + ldRow) * K + kc + q * 8);
        }
    }

    __device__ __forceinline__ void chunk_mma(int s, float acc[4][4][4]) const {
        const uint32_t abase = sbase + s * STAGE_B;
        const uint32_t bbase = abase + T_STAGE;
#pragma unroll
        for (int ks = 0; ks < 4; ks++) {
            const uint32_t kb = (uint32_t)ks * 32;
            uint32_t af[4][4], bf[4][2];
#pragma unroll
            for (int i = 0; i < 4; i++) {
                const uint32_t ad = abase + (uint32_t)(mW + i * 16) * ROWB + kb + offA;
                LDSM_X4(af[i][0], af[i][1], af[i][2], af[i][3], ad);
            }
#pragma unroll
            for (int jp = 0; jp < 2; jp++) {
                const uint32_t bd = bbase + (uint32_t)(nW + jp * 16) * ROWB + kb + offB;
                LDSM_X4(bf[2 * jp][0], bf[2 * jp][1], bf[2 * jp + 1][0], bf[2 * jp + 1][1], bd);
            }
#pragma unroll
            for (int i = 0; i < 4; i++)
#pragma unroll
                for (int j = 0; j < 4; j++)
                    mma_f16(acc[i][j], af[i], bf[j]);
        }
    }
};

#define ACC_INIT(acc) \
    _Pragma("unroll") for (int i = 0; i < 4; i++) \
    _Pragma("unroll") for (int j = 0; j < 4; j++) \
    _Pragma("unroll") for (int r = 0; r < 4; r++) acc[i][j][r] = 0.0f;

__device__ __forceinline__ void kloopP(const GemmCore& g, const __half* A,
                                       const __half* Bt, int m0, int n0, int K,
                                       float acc[4][4][4]) {
    const int NT = K >> 6;
    g.load_stageP(A, Bt, m0, n0, K, 0, 0); CP_COMMIT();
    g.load_stageP(A, Bt, m0, n0, K, 64, 1); CP_COMMIT();
    for (int t = 0; t < NT; t++) {
        if (t + 1 < NT) { CP_WAIT(1); } else { CP_WAIT(0); }
        __syncthreads();
        if (t + 2 < NT) { g.load_stageP(A, Bt, m0, n0, K, (t + 2) << 6, (t + 2) % NSTAGE); CP_COMMIT(); }
        g.chunk_mma(t % NSTAGE, acc);
    }
}
__device__ __forceinline__ void kloopC(const GemmCore& g, const __half* A,
                                       const __half* A2, const __half* Bt,
                                       int m0, int n0, int K, float acc[4][4][4]) {
    const int NT = K >> 6;
    g.load_stage(A, A2, Bt, m0, n0, K, 0, 0); CP_COMMIT();
    g.load_stage(A, A2, Bt, m0, n0, K, 64, 1); CP_COMMIT();
    for (int t = 0; t < NT; t++) {
        if (t + 1 < NT) { CP_WAIT(1); } else { CP_WAIT(0); }
        __syncthreads();
        if (t + 2 < NT) { g.load_stage(A, A2, Bt, m0, n0, K, (t + 2) << 6, (t + 2) % NSTAGE); CP_COMMIT(); }
        g.chunk_mma(t % NSTAGE, acc);
    }
}

// ---------------- mega-kernel: prep + all 6 GEMMs, producers-first ---------
// idx [0,248)      : weight transposes (5 slices)    -> g_wcnt[0..4]
// idx [248,264)    : ppf conversion                  -> g_wcnt[5]
// idx [264,648)    : input conv per (z, mb)          -> g_conv[z*128+mb]
// idx [648,2184)   : s1   (waits weights + conv)     -> g_cnt_s1
// idx [2184,2696)  : pf   (waits Wtf + ppf + Hv)     -> g_cnt_pf
// idx [2696,4744)  : s/o  (waits Wt2 + Hs/Ho)
// idx [4744,5000)  : pred (waits Wtp + Hp)
__global__ void __launch_bounds__(256, 2)
mega(const float* __restrict__ inp_sf, const float* __restrict__ inp_of,
     const float* __restrict__ inp_pvf, const float* __restrict__ inp_ppf,
     const float* __restrict__ W_obj1, const float* __restrict__ W_pvf,
     const float* __restrict__ W_pf, const float* __restrict__ W_obj2,
     const float* __restrict__ W_pred,
     const float* __restrict__ b_obj1, const float* __restrict__ b_pvf,
     const float* __restrict__ b_pf,
     float* __restrict__ out_s, float* __restrict__ out_o,
     float* __restrict__ out_p,
     const int* __restrict__ gts, const int* __restrict__ gto,
     const float* __restrict__ so2p, const float* __restrict__ sof)
{
    extern __shared__ __align__(16) char smem[];
    const int idx = blockIdx.x;

    if (idx < 648) {                        // ======== prep roles ========
        if (idx < 248) {
            int w, base, n;
            if (idx < 64)       { w = 0; base = 0;   n = 64; }
            else if (idx < 128) { w = 1; base = 64;  n = 64; }
            else if (idx < 168) { w = 2; base = 128; n = 40; }
            else if (idx < 232) { w = 3; base = 168; n = 64; }
            else                { w = 4; base = 232; n = 16; }
            const float* W; __half* Wt; int K, N, Npad;
            switch (w) {
                case 0:  W = W_obj1; Wt = g_Wt1; K = OBJ_FEAT; N = HIDDEN;  Npad = HIDDEN;  break;
                case 1:  W = W_pvf;  Wt = g_Wtv; K = PVF_DIM;  N = HIDDEN;  Npad = HIDDEN;  break;
                case 2:  W = W_pf;   Wt = g_Wtf; K = HIDDEN + PPF_DIM; N = HIDDEN; Npad = HIDDEN; break;
                case 3:  W = W_obj2; Wt = g_Wt2; K = HIDDEN;   N = OBJ_NUM; Npad = OBJ_PAD; break;
                default: W = W_pred; Wt = g_Wtp; K = HIDDEN;   N = PRED_NUM; Npad = PRED_PAD; break;
            }
            transpose_slice(smem, W, Wt, K, N, Npad, idx - base, n);
            signal_done(&g_wcnt[w]);
        } else if (idx < 264) {
            const int sl = idx - 248;                 // 16 slices
            const int total = BQ * PPF_DIM / 8;       // 131072 units
            const int per = total / 16;
            conv_units(inp_ppf, g_ppfh, (size_t)sl * per, per);
            signal_done(&g_wcnt[5]);
        } else {
            const int r = idx - 264;                  // 0..383
            const int z = r >> 7, mb = r & 127;
            const float* in = (z == 0) ? inp_sf : (z == 1) ? inp_of : inp_pvf;
            __half* out = (z == 0) ? g_sfh : (z == 1) ? g_ofh : g_pvfh;
            // m-block = 128 rows x 1024 cols = 16384 8-elem units
            conv_units(in, out, (size_t)mb * 16384, 16384);
            signal_done(&g_conv[r]);
        }
        return;
    }

    GemmCore g; g.init(smem_u32(smem));
    float acc[4][4][4];
    ACC_INIT(acc);
    const int gi = idx - 648;

    if (gi < 1536) {                        // ---- stage 1 ----
        const int z = gi >> 9, rem = gi & 511;
        const int n0 = (rem & 3) * 128, mb = rem >> 2, m0 = mb * 128;
        waits(&g_wcnt[(z == 2) ? 1 : 0], 64, &g_conv[z * MBLK + mb], 1, nullptr, 0);

        const __half* A  = (z == 0) ? g_sfh : (z == 1) ? g_ofh : g_pvfh;
        const __half* Bt = (z == 2) ? g_Wtv : g_Wt1;
        const float* bias = (z == 2) ? b_pvf : b_obj1;
        __half* C = (z == 0) ? g_Hs : (z == 1) ? g_Ho : g_Hv;

        kloopP(g, A, Bt, m0, n0, OBJ_FEAT, acc);

#pragma unroll
        for (int i = 0; i < 4; i++)
#pragma unroll
            for (int half = 0; half < 2; half++) {
                const int gm = m0 + g.mW + i * 16 + g.grp + half * 8;
                __half* crow = C + (size_t)gm * HIDDEN;
#pragma unroll
                for (int j = 0; j < 4; j++) {
                    const int gn = n0 + g.nW + j * 8 + g.t4 * 2;
                    const float a0 = fmaxf(acc[i][j][half * 2 + 0] + bias[gn], 0.0f);
                    const float a1 = fmaxf(acc[i][j][half * 2 + 1] + bias[gn + 1], 0.0f);
                    *reinterpret_cast<__half2*>(crow + gn) = __floats2half2_rn(a0, a1);
                }
            }
        signal_done(&g_cnt_s1[z * MBLK + mb]);

    } else if (gi < 2048) {                 // ---- pf_emb ----
        const int rem = gi - 1536;
        const int n0 = (rem & 3) * 128, mb = rem >> 2, m0 = mb * 128;
        waits(&g_wcnt[2], 40, &g_wcnt[5], 16, &g_cnt_s1[2 * MBLK + mb], 4);

        kloopC(g, g_Hv, g_ppfh, g_Wtf, m0, n0, HIDDEN + PPF_DIM, acc);

#pragma unroll
        for (int i = 0; i < 4; i++)
#pragma unroll
            for (int half = 0; half < 2; half++) {
                const int gm = m0 + g.mW + i * 16 + g.grp + half * 8;
                __half* crow = g_Hp + (size_t)gm * HIDDEN;
#pragma unroll
                for (int j = 0; j < 4; j++) {
                    const int gn = n0 + g.nW + j * 8 + g.t4 * 2;
                    const float a0 = fmaxf(acc[i][j][half * 2 + 0] + b_pf[gn], 0.0f);
                    const float a1 = fmaxf(acc[i][j][half * 2 + 1] + b_pf[gn + 1], 0.0f);
                    *reinterpret_cast<__half2*>(crow + gn) = __floats2half2_rn(a0, a1);
                }
            }
        signal_done(&g_cnt_pf[mb]);

    } else if (gi < 4096) {                 // ---- s / o scores ----
        const int rem = gi - 2048;
        const int z = rem >> 10, rem2 = rem & 1023;
        const int n0 = (rem2 & 7) * 128, mb = rem2 >> 3, m0 = mb * 128;
        waits(&g_wcnt[3], 64, &g_cnt_s1[z * MBLK + mb], 4, nullptr, 0);

        const __half* A = z ? g_Ho : g_Hs;
        float* C = z ? out_o : out_s;

        kloopC(g, A, g_ppfh, g_Wt2, m0, n0, HIDDEN, acc);

#pragma unroll
        for (int i = 0; i < 4; i++)
#pragma unroll
            for (int half = 0; half < 2; half++) {
                const int gm = m0 + g.mW + i * 16 + g.grp + half * 8;
                float* crow = C + (size_t)gm * OBJ_NUM;
#pragma unroll
                for (int j = 0; j < 4; j++) {
                    const int gn = n0 + g.nW + j * 8 + g.t4 * 2;
                    if (gn < OBJ_NUM)     crow[gn]     = acc[i][j][half * 2 + 0];
                    if (gn + 1 < OBJ_NUM) crow[gn + 1] = acc[i][j][half * 2 + 1];
                }
            }

    } else {                                // ---- predicate + so2p ----
        const int rem = gi - 4096;
        const int n0 = (rem & 1) * 128, mb = rem >> 1, m0 = mb * 128;
        waits(&g_wcnt[4], 16, &g_cnt_pf[mb], 4, nullptr, 0);

        kloopC(g, g_Hp, g_ppfh, g_Wtp, m0, n0, HIDDEN, acc);

        const float ef = expf(sof[0]);
#pragma unroll
        for (int i = 0; i < 4; i++)
#pragma unroll
            for (int half = 0; half < 2; half++) {
                const int gm = m0 + g.mW + i * 16 + g.grp + half * 8;
                const size_t sob = ((size_t)gts[gm] * OBJ_NUM + (size_t)gto[gm]) * (size_t)PRED_NUM;
                float* crow = out_p + (size_t)gm * PRED_NUM;
#pragma unroll
                for (int j = 0; j < 4; j++) {
                    const int gn = n0 + g.nW + j * 8 + g.t4 * 2;
                    const float v0 = acc[i][j][half * 2 + 0];
                    const float v1 = acc[i][j][half * 2 + 1];
                    if (gn < PRED_NUM)     crow[gn]     = v0 + so2p[sob + gn] * ef;
                    if (gn + 1 < PRED_NUM) crow[gn + 1] = v1 + so2p[sob + gn + 1] * ef;
                }
            }
    }
}

// ---------------- host ----------------
extern "C" void kernel_launch(void* const* d_in, const int* in_sizes, int n_in,
                              void* d_out, int out_size)
{
    const float* inp_sf  = (const float*)d_in[0];
    const float* inp_of  = (const float*)d_in[1];
    const float* inp_ppf = (const float*)d_in[2];
    const float* inp_pvf = (const float*)d_in[3];
    const int*   gt_s    = (const int*)d_in[4];
    const int*   gt_o    = (const int*)d_in[5];
    const float* W_obj1  = (const float*)d_in[6];
    const float* b_obj1  = (const float*)d_in[7];
    const float* W_obj2  = (const float*)d_in[8];
    const float* W_pvf   = (const float*)d_in[9];
    const float* b_pvf   = (const float*)d_in[10];
    const float* W_pf    = (const float*)d_in[11];
    const float* b_pf    = (const float*)d_in[12];
    const float* W_pred  = (const float*)d_in[13];
    const float* so2p    = (const float*)d_in[14];
    const float* sof     = (const float*)d_in[15];

    float* out   = (float*)d_out;
    float* out_s = out;
    float* out_o = out + (size_t)BQ * OBJ_NUM;
    float* out_p = out + (size_t)2 * BQ * OBJ_NUM;

    cudaFuncSetAttribute(mega, cudaFuncAttributeMaxDynamicSharedMemorySize, SMEM_BYTES);

    clearflags<<<1, 256>>>();
    mega<<<5000, 256, SMEM_BYTES>>>(inp_sf, inp_of, inp_pvf, inp_ppf,
                                    W_obj1, W_pvf, W_pf, W_obj2, W_pred,
                                    b_obj1, b_pvf, b_pf,
                                    out_s, out_o, out_p,
                                    gt_s, gt_o, so2p, sof);
}

// round 16
// speedup vs baseline: 1.0397x; 1.0397x over previous
#include <cuda_runtime.h>
#include <cuda_fp16.h>
#include <math.h>
#include <stdint.h>

#define BQ        16384
#define OBJ_FEAT  1024
#define PVF_DIM   1024
#define PPF_DIM   64
#define HIDDEN    512
#define OBJ_NUM   1001
#define PRED_NUM  132

#define OBJ_PAD   1024
#define PRED_PAD  256
#define MBLK      (BQ / 128)                    // 128 m-blocks

// ---------------- scratch (__device__ globals; allocation-free rule) --------
__device__ __half g_sfh[(size_t)BQ * OBJ_FEAT];
__device__ __half g_ofh[(size_t)BQ * OBJ_FEAT];
__device__ __half g_pvfh[(size_t)BQ * PVF_DIM];
__device__ __half g_ppfh[(size_t)BQ * PPF_DIM];
__device__ __half g_Hs[(size_t)BQ * HIDDEN];
__device__ __half g_Ho[(size_t)BQ * HIDDEN];
__device__ __half g_Hv[(size_t)BQ * HIDDEN];
__device__ __half g_Hp[(size_t)BQ * HIDDEN];
__device__ __half g_Wt1[(size_t)HIDDEN * OBJ_FEAT];            // [512][1024]
__device__ __half g_Wtv[(size_t)HIDDEN * PVF_DIM];             // [512][1024]
__device__ __half g_Wtf[(size_t)HIDDEN * (HIDDEN + PPF_DIM)];  // [512][576]
__device__ __half g_Wt2[(size_t)OBJ_PAD * HIDDEN];             // [1024][512]
__device__ __half g_Wtp[(size_t)PRED_PAD * HIDDEN];            // [256][512]

// per-row-block completion counters (cleared by prep each run)
__device__ int g_cnt_s1[3 * MBLK];              // s1 z-slice, 4 n-tiles each
__device__ int g_cnt_pf[MBLK];                  // pf, 4 n-tiles each

// ---------------- PTX helpers ----------------
__device__ __forceinline__ uint32_t smem_u32(const void* p) {
    uint32_t a;
    asm("{ .reg .u64 t; cvta.to.shared.u64 t, %1; cvt.u32.u64 %0, t; }" : "=r"(a) : "l"(p));
    return a;
}
__device__ __forceinline__ void mma_f16(float* c, const uint32_t* a, const uint32_t* b) {
    asm volatile(
        "mma.sync.aligned.m16n8k16.row.col.f32.f16.f16.f32 "
        "{%0,%1,%2,%3}, {%4,%5,%6,%7}, {%8,%9}, {%0,%1,%2,%3};"
        : "+f"(c[0]), "+f"(c[1]), "+f"(c[2]), "+f"(c[3])
        : "r"(a[0]), "r"(a[1]), "r"(a[2]), "r"(a[3]), "r"(b[0]), "r"(b[1]));
}
#define LDSM_X4(r0, r1, r2, r3, addr) \
    asm volatile("ldmatrix.sync.aligned.m8n8.x4.shared.b16 {%0,%1,%2,%3}, [%4];" \
        : "=r"(r0), "=r"(r1), "=r"(r2), "=r"(r3) : "r"(addr))
__device__ __forceinline__ void cp16cg(uint32_t dst, const void* src) {
    asm volatile("cp.async.cg.shared.global [%0], [%1], 16;" :: "r"(dst), "l"(src));
}
__device__ __forceinline__ void cp16ca(uint32_t dst, const void* src) {
    asm volatile("cp.async.ca.shared.global [%0], [%1], 16;" :: "r"(dst), "l"(src));
}
#define CP_COMMIT() asm volatile("cp.async.commit_group;" ::: "memory")
#define CP_WAIT(n)  asm volatile("cp.async.wait_group %0;" :: "n"(n) : "memory")

// producer handoff: all stores visible, then one count
__device__ __forceinline__ void signal_done(int* c) {
    __threadfence();
    __syncthreads();
    if (threadIdx.x == 0) atomicAdd(c, 1);
}
// consumer: spin until target n-tiles done
__device__ __forceinline__ void wait_cnt(int* c, int target) {
    if (threadIdx.x == 0) {
        while (atomicAdd(c, 0) < target) __nanosleep(64);
        __threadfence();
    }
    __syncthreads();
}

// ---------------- smem layout: 3 stages, A/B tiles [128 rows][64+8 halves] --
#define ROWB      144                           // 128B data + 16B pad
#define T_STAGE   (128 * ROWB)                  // 18432 B
#define STAGE_B   (2 * T_STAGE)                 // 36864 B (A then B)
#define NSTAGE    3
#define SMEM_BYTES (NSTAGE * STAGE_B)           // 110592 B

// ---------------- fused prep: flag clear + conversions + transposes --------
__global__ void prep(const float* __restrict__ sf, const float* __restrict__ of,
                     const float* __restrict__ pvf, const float* __restrict__ ppf,
                     __half* __restrict__ sfh, __half* __restrict__ ofh,
                     __half* __restrict__ pvfh, __half* __restrict__ ppfh,
                     const float* __restrict__ W1, const float* __restrict__ Wv,
                     const float* __restrict__ Wf, const float* __restrict__ W2,
                     const float* __restrict__ Wp,
                     __half* __restrict__ Wt1, __half* __restrict__ Wtv,
                     __half* __restrict__ Wtf, __half* __restrict__ Wt2,
                     __half* __restrict__ Wtp)
{
    const int z = blockIdx.z;
    if (z == 0 && blockIdx.x == 0) {            // reset flags for this replay
        for (int i = threadIdx.x; i < 3 * MBLK; i += blockDim.x) g_cnt_s1[i] = 0;
        for (int i = threadIdx.x; i < MBLK; i += blockDim.x) g_cnt_pf[i] = 0;
    }
    if (z < 4) {
        const float* in = (z == 0) ? sf : (z == 1) ? of : (z == 2) ? pvf : ppf;
        __half* out = (z == 0) ? sfh : (z == 1) ? ofh : (z == 2) ? pvfh : ppfh;
        const int n8 = (z == 3) ? (BQ * PPF_DIM / 8) : (BQ * OBJ_FEAT / 8);
        for (int i = blockIdx.x * blockDim.x + threadIdx.x; i < n8;
             i += gridDim.x * blockDim.x) {
            const float4 a = *reinterpret_cast<const float4*>(in + (size_t)i * 8);
            const float4 b = *reinterpret_cast<const float4*>(in + (size_t)i * 8 + 4);
            __half2 h[4];
            h[0] = __floats2half2_rn(a.x, a.y);
            h[1] = __floats2half2_rn(a.z, a.w);
            h[2] = __floats2half2_rn(b.x, b.y);
            h[3] = __floats2half2_rn(b.z, b.w);
            *reinterpret_cast<uint4*>(out + (size_t)i * 8) = *reinterpret_cast<uint4*>(h);
        }
    } else {
        const float* W; __half* Wt; int K, N, Npad;
        switch (z) {
            case 4: W = W1; Wt = Wt1; K = OBJ_FEAT; N = HIDDEN; Npad = HIDDEN; break;
            case 5: W = Wv; Wt = Wtv; K = PVF_DIM;  N = HIDDEN; Npad = HIDDEN; break;
            case 6: W = Wf; Wt = Wtf; K = HIDDEN + PPF_DIM; N = HIDDEN; Npad = HIDDEN; break;
            case 7: W = W2; Wt = Wt2; K = HIDDEN; N = OBJ_NUM;  Npad = OBJ_PAD; break;
            default: W = Wp; Wt = Wtp; K = HIDDEN; N = PRED_NUM; Npad = PRED_PAD; break;
        }
        __shared__ float t[32][33];
        const int tx5 = threadIdx.x & 31, ty3 = threadIdx.x >> 5;  // (32, 8)
        const int ntx = Npad / 32, nty = (K + 31) / 32;
        for (int tile = blockIdx.x; tile < ntx * nty; tile += gridDim.x) {
            const int bx = (tile % ntx) * 32;   // n
            const int by = (tile / ntx) * 32;   // k
#pragma unroll
            for (int j = 0; j < 32; j += 8) {
                const int y = by + ty3 + j, x = bx + tx5;
                t[ty3 + j][tx5] = (x < N && y < K) ? W[(size_t)y * N + x] : 0.0f;
            }
            __syncthreads();
#pragma unroll
            for (int j = 0; j < 32; j += 8) {
                const int row = bx + ty3 + j, col = by + tx5;
                if (row < Npad && col < K)
                    Wt[(size_t)row * K + col] = __float2half(t[tx5][ty3 + j]);
            }
            __syncthreads();
        }
    }
}

// ================= round-6 champion GEMM core (unchanged) ==================
struct GemmCore {
    uint32_t sbase;
    int tid, lane, grp, t4, mW, nW;
    uint32_t offA, offB;
    int ldRow, ldQ0;

    __device__ __forceinline__ void init(uint32_t sb) {
        sbase = sb;
        tid = threadIdx.x;
        const int wid = tid >> 5;
        lane = tid & 31;
        grp = lane >> 2; t4 = lane & 3;
        const int wy = wid >> 2, wx = wid & 3;     // warp grid 2x4
        mW = wy * 64; nW = wx * 32;
        offA = (uint32_t)(lane & 15) * ROWB + (uint32_t)(lane >> 4) * 16;
        const uint32_t bR = (uint32_t)((lane & 7) + ((lane >> 4) & 1) * 8);
        offB = bR * ROWB + (uint32_t)((lane >> 3) & 1) * 16;
        ldRow = tid >> 1;
        ldQ0 = (tid & 1) * 4;
    }

    __device__ __forceinline__ void load_stage(const __half* __restrict__ A,
                                               const __half* __restrict__ A2,
                                               const __half* __restrict__ Bt,
                                               int m0, int n0, int K,
                                               int kc, int s) const {
        const uint32_t abase = sbase + s * STAGE_B;
        const uint32_t bbase = abase + T_STAGE;
#pragma unroll
        for (int i = 0; i < 4; i++) {
            const int q = ldQ0 + i;
            const int k = kc + q * 8;
            const uint32_t dst = abase + (uint32_t)ldRow * ROWB + (uint32_t)q * 16;
            const __half* src = (k < HIDDEN)
                ? (A  + (size_t)(m0 + ldRow) * HIDDEN + k)
                : (A2 + (size_t)(m0 + ldRow) * PPF_DIM + (k - HIDDEN));
            cp16cg(dst, src);
        }
#pragma unroll
        for (int i = 0; i < 4; i++) {
            const int q = ldQ0 + i;
            const uint32_t dst = bbase + (uint32_t)ldRow * ROWB + (uint32_t)q * 16;
            cp16ca(dst, Bt + (size_t)(n0 + ldRow) * K + kc + q * 8);
        }
    }

    __device__ __forceinline__ void load_stageP(const __half* __restrict__ A,
                                                const __half* __restrict__ Bt,
                                                int m0, int n0, int K,
                                                int kc, int s) const {
        const uint32_t abase = sbase + s * STAGE_B;
        const uint32_t bbase = abase + T_STAGE;
#pragma unroll
        for (int i = 0; i < 4; i++) {
            const int q = ldQ0 + i;
            const uint32_t dst = abase + (uint32_t)ldRow * ROWB + (uint32_t)q * 16;
            cp16cg(dst, A + (size_t)(m0 + ldRow) * K + kc + q * 8);
        }
#pragma unroll
        for (int i = 0; i < 4; i++) {
            const int q = ldQ0 + i;
            const uint32_t dst = bbase + (uint32_t)ldRow * ROWB + (uint32_t)q * 16;
            cp16ca(dst, Bt + (size_t)(n0 + ldRow) * K + kc + q * 8);
        }
    }

    __device__ __forceinline__ void chunk_mma(int s, float acc[4][4][4]) const {
        const uint32_t abase = sbase + s * STAGE_B;
        const uint32_t bbase = abase + T_STAGE;
#pragma unroll
        for (int ks = 0; ks < 4; ks++) {
            const uint32_t kb = (uint32_t)ks * 32;
            uint32_t af[4][4], bf[4][2];
#pragma unroll
            for (int i = 0; i < 4; i++) {
                const uint32_t ad = abase + (uint32_t)(mW + i * 16) * ROWB + kb + offA;
                LDSM_X4(af[i][0], af[i][1], af[i][2], af[i][3], ad);
            }
#pragma unroll
            for (int jp = 0; jp < 2; jp++) {
                const uint32_t bd = bbase + (uint32_t)(nW + jp * 16) * ROWB + kb + offB;
                LDSM_X4(bf[2 * jp][0], bf[2 * jp][1], bf[2 * jp + 1][0], bf[2 * jp + 1][1], bd);
            }
#pragma unroll
            for (int i = 0; i < 4; i++)
#pragma unroll
                for (int j = 0; j < 4; j++)
                    mma_f16(acc[i][j], af[i], bf[j]);
        }
    }
};

#define ACC_INIT(acc) \
    _Pragma("unroll") for (int i = 0; i < 4; i++) \
    _Pragma("unroll") for (int j = 0; j < 4; j++) \
    _Pragma("unroll") for (int r = 0; r < 4; r++) acc[i][j][r] = 0.0f;

__device__ __forceinline__ void kloopP(const GemmCore& g, const __half* A,
                                       const __half* Bt, int m0, int n0, int K,
                                       float acc[4][4][4]) {
    const int NT = K >> 6;
    g.load_stageP(A, Bt, m0, n0, K, 0, 0); CP_COMMIT();
    g.load_stageP(A, Bt, m0, n0, K, 64, 1); CP_COMMIT();
    for (int t = 0; t < NT; t++) {
        if (t + 1 < NT) { CP_WAIT(1); } else { CP_WAIT(0); }
        __syncthreads();
        if (t + 2 < NT) { g.load_stageP(A, Bt, m0, n0, K, (t + 2) << 6, (t + 2) % NSTAGE); CP_COMMIT(); }
        g.chunk_mma(t % NSTAGE, acc);
    }
}
__device__ __forceinline__ void kloopC(const GemmCore& g, const __half* A,
                                       const __half* A2, const __half* Bt,
                                       int m0, int n0, int K, float acc[4][4][4]) {
    const int NT = K >> 6;
    g.load_stage(A, A2, Bt, m0, n0, K, 0, 0); CP_COMMIT();
    g.load_stage(A, A2, Bt, m0, n0, K, 64, 1); CP_COMMIT();
    for (int t = 0; t < NT; t++) {
        if (t + 1 < NT) { CP_WAIT(1); } else { CP_WAIT(0); }
        __syncthreads();
        if (t + 2 < NT) { g.load_stage(A, A2, Bt, m0, n0, K, (t + 2) << 6, (t + 2) % NSTAGE); CP_COMMIT(); }
        g.chunk_mma(t % NSTAGE, acc);
    }
}

// ---------------- mega-kernel: all 6 GEMMs, deep-chain-first dispatch ------
// idx [0,512)     : s1 z2 (pvf)  -- head of the 3-deep chain, dispatched FIRST
// idx [512,1536)  : s1 z0/z1
// idx [1536,2048) : pf   (waits Hv)
// idx [2048,2304) : pred (waits Hp) -- dispatched BEFORE the s/o bulk
// idx [2304,4352) : s/o  (waits Hs/Ho) -- bulk fills the tail
__global__ void __launch_bounds__(256, 2)
gemm_all(const float* __restrict__ b_obj1, const float* __restrict__ b_pvf,
         const float* __restrict__ b_pf,
         float* __restrict__ out_s, float* __restrict__ out_o,
         float* __restrict__ out_p,
         const int* __restrict__ gts, const int* __restrict__ gto,
         const float* __restrict__ so2p, const float* __restrict__ sof)
{
    extern __shared__ __align__(16) char smem[];
    GemmCore g; g.init(smem_u32(smem));
    const int idx = blockIdx.x;

    float acc[4][4][4];
    ACC_INIT(acc);

    if (idx < 1536) {                       // ---- stage 1 (z2 first) ----
        const int z = (idx < 512) ? 2 : ((idx - 512) >> 9);
        const int rem = (idx < 512) ? idx : ((idx - 512) & 511);
        const int n0 = (rem & 3) * 128, mb = rem >> 2, m0 = mb * 128;
        const __half* A  = (z == 0) ? g_sfh : (z == 1) ? g_ofh : g_pvfh;
        const __half* Bt = (z == 2) ? g_Wtv : g_Wt1;
        const float* bias = (z == 2) ? b_pvf : b_obj1;
        __half* C = (z == 0) ? g_Hs : (z == 1) ? g_Ho : g_Hv;

        kloopP(g, A, Bt, m0, n0, OBJ_FEAT, acc);

#pragma unroll
        for (int i = 0; i < 4; i++)
#pragma unroll
            for (int half = 0; half < 2; half++) {
                const int gm = m0 + g.mW + i * 16 + g.grp + half * 8;
                __half* crow = C + (size_t)gm * HIDDEN;
#pragma unroll
                for (int j = 0; j < 4; j++) {
                    const int gn = n0 + g.nW + j * 8 + g.t4 * 2;
                    const float a0 = fmaxf(acc[i][j][half * 2 + 0] + bias[gn], 0.0f);
                    const float a1 = fmaxf(acc[i][j][half * 2 + 1] + bias[gn + 1], 0.0f);
                    *reinterpret_cast<__half2*>(crow + gn) = __floats2half2_rn(a0, a1);
                }
            }
        signal_done(&g_cnt_s1[z * MBLK + mb]);

    } else if (idx < 2048) {                // ---- pf_emb ----
        const int rem = idx - 1536;
        const int n0 = (rem & 3) * 128, mb = rem >> 2, m0 = mb * 128;
        wait_cnt(&g_cnt_s1[2 * MBLK + mb], 4);

        kloopC(g, g_Hv, g_ppfh, g_Wtf, m0, n0, HIDDEN + PPF_DIM, acc);

#pragma unroll
        for (int i = 0; i < 4; i++)
#pragma unroll
            for (int half = 0; half < 2; half++) {
                const int gm = m0 + g.mW + i * 16 + g.grp + half * 8;
                __half* crow = g_Hp + (size_t)gm * HIDDEN;
#pragma unroll
                for (int j = 0; j < 4; j++) {
                    const int gn = n0 + g.nW + j * 8 + g.t4 * 2;
                    const float a0 = fmaxf(acc[i][j][half * 2 + 0] + b_pf[gn], 0.0f);
                    const float a1 = fmaxf(acc[i][j][half * 2 + 1] + b_pf[gn + 1], 0.0f);
                    *reinterpret_cast<__half2*>(crow + gn) = __floats2half2_rn(a0, a1);
                }
            }
        signal_done(&g_cnt_pf[mb]);

    } else if (idx < 2304) {                // ---- predicate + so2p ----
        const int rem = idx - 2048;
        const int n0 = (rem & 1) * 128, mb = rem >> 1, m0 = mb * 128;
        wait_cnt(&g_cnt_pf[mb], 4);

        kloopC(g, g_Hp, g_ppfh, g_Wtp, m0, n0, HIDDEN, acc);

        const float ef = expf(sof[0]);
#pragma unroll
        for (int i = 0; i < 4; i++)
#pragma unroll
            for (int half = 0; half < 2; half++) {
                const int gm = m0 + g.mW + i * 16 + g.grp + half * 8;
                const size_t sob = ((size_t)gts[gm] * OBJ_NUM + (size_t)gto[gm]) * (size_t)PRED_NUM;
                float* crow = out_p + (size_t)gm * PRED_NUM;
#pragma unroll
                for (int j = 0; j < 4; j++) {
                    const int gn = n0 + g.nW + j * 8 + g.t4 * 2;
                    const float v0 = acc[i][j][half * 2 + 0];
                    const float v1 = acc[i][j][half * 2 + 1];
                    if (gn < PRED_NUM)     crow[gn]     = v0 + so2p[sob + gn] * ef;
                    if (gn + 1 < PRED_NUM) crow[gn + 1] = v1 + so2p[sob + gn + 1] * ef;
                }
            }

    } else {                                // ---- s / o scores (bulk tail) --
        const int rem = idx - 2304;
        const int z = rem >> 10, rem2 = rem & 1023;
        const int n0 = (rem2 & 7) * 128, mb = rem2 >> 3, m0 = mb * 128;
        wait_cnt(&g_cnt_s1[z * MBLK + mb], 4);

        const __half* A = z ? g_Ho : g_Hs;
        float* C = z ? out_o : out_s;

        kloopC(g, A, g_ppfh, g_Wt2, m0, n0, HIDDEN, acc);

#pragma unroll
        for (int i = 0; i < 4; i++)
#pragma unroll
            for (int half = 0; half < 2; half++) {
                const int gm = m0 + g.mW + i * 16 + g.grp + half * 8;
                float* crow = C + (size_t)gm * OBJ_NUM;
#pragma unroll
                for (int j = 0; j < 4; j++) {
                    const int gn = n0 + g.nW + j * 8 + g.t4 * 2;
                    if (gn < OBJ_NUM)     crow[gn]     = acc[i][j][half * 2 + 0];
                    if (gn + 1 < OBJ_NUM) crow[gn + 1] = acc[i][j][half * 2 + 1];
                }
            }
    }
}

// ---------------- host ----------------
extern "C" void kernel_launch(void* const* d_in, const int* in_sizes, int n_in,
                              void* d_out, int out_size)
{
    const float* inp_sf  = (const float*)d_in[0];
    const float* inp_of  = (const float*)d_in[1];
    const float* inp_ppf = (const float*)d_in[2];
    const float* inp_pvf = (const float*)d_in[3];
    const int*   gt_s    = (const int*)d_in[4];
    const int*   gt_o    = (const int*)d_in[5];
    const float* W_obj1  = (const float*)d_in[6];
    const float* b_obj1  = (const float*)d_in[7];
    const float* W_obj2  = (const float*)d_in[8];
    const float* W_pvf   = (const float*)d_in[9];
    const float* b_pvf   = (const float*)d_in[10];
    const float* W_pf    = (const float*)d_in[11];
    const float* b_pf    = (const float*)d_in[12];
    const float* W_pred  = (const float*)d_in[13];
    const float* so2p    = (const float*)d_in[14];
    const float* sof     = (const float*)d_in[15];

    float* out   = (float*)d_out;
    float* out_s = out;
    float* out_o = out + (size_t)BQ * OBJ_NUM;
    float* out_p = out + (size_t)2 * BQ * OBJ_NUM;

    __half *sfh, *ofh, *pvfh, *ppfh, *Wt1, *Wtv, *Wtf, *Wt2, *Wtp;
    cudaGetSymbolAddress((void**)&sfh,  g_sfh);
    cudaGetSymbolAddress((void**)&ofh,  g_ofh);
    cudaGetSymbolAddress((void**)&pvfh, g_pvfh);
    cudaGetSymbolAddress((void**)&ppfh, g_ppfh);
    cudaGetSymbolAddress((void**)&Wt1, g_Wt1);
    cudaGetSymbolAddress((void**)&Wtv, g_Wtv);
    cudaGetSymbolAddress((void**)&Wtf, g_Wtf);
    cudaGetSymbolAddress((void**)&Wt2, g_Wt2);
    cudaGetSymbolAddress((void**)&Wtp, g_Wtp);

    cudaFuncSetAttribute(gemm_all, cudaFuncAttributeMaxDynamicSharedMemorySize, SMEM_BYTES);

    // prep: flag clear + 4 conversions + 5 transpose/pad/convert
    prep<<<dim3(512, 1, 9), 256>>>(inp_sf, inp_of, inp_pvf, inp_ppf,
                                   sfh, ofh, pvfh, ppfh,
                                   W_obj1, W_pvf, W_pf, W_obj2, W_pred,
                                   Wt1, Wtv, Wtf, Wt2, Wtp);

    // all six GEMMs in one launch; deep chain (z2 -> pf -> pred) first,
    // s/o bulk last to absorb the chain's tail
    gemm_all<<<4352, 256, SMEM_BYTES>>>(b_obj1, b_pvf, b_pf,
                                        out_s, out_o, out_p,
                                        gt_s, gt_o, so2p, sof);
}